// round 1
// baseline (speedup 1.0000x reference)
#include <cuda_runtime.h>
#include <cuda_bf16.h>

#define NN 100000
#define DD 64

// scratch (no allocations allowed)
__device__ __align__(16) float g_h[NN * DD];     // SpMM result
__device__ __align__(16) float g_y[NN * DD];     // pre-BN activations
__device__ float g_stats[128];                   // [0:64) sum, [64:128) sumsq
__device__ float g_scale[DD];
__device__ float g_shift[DD];

// ---------------------------------------------------------------------------
// K1: zero h + stats
__global__ void k_zero(int n4) {
    float4* h4 = reinterpret_cast<float4*>(g_h);
    int gid = blockIdx.x * blockDim.x + threadIdx.x;
    if (gid < 128) g_stats[gid] = 0.0f;
    for (int i = gid; i < n4; i += gridDim.x * blockDim.x)
        h4[i] = make_float4(0.f, 0.f, 0.f, 0.f);
}

// ---------------------------------------------------------------------------
// K2: COO SpMM  h[row] += val * x[col]   (16 threads per edge, vector red)
__global__ void k_spmm(const float* __restrict__ x,
                       const float* __restrict__ val,
                       const int* __restrict__ row,
                       const int* __restrict__ col,
                       int E) {
    long total = (long)E * 16;
    long stride = (long)gridDim.x * blockDim.x;
    for (long i = (long)blockIdx.x * blockDim.x + threadIdx.x; i < total; i += stride) {
        int e = (int)(i >> 4);
        int k = (int)(i & 15);          // which float4 of the 64-dim row
        int r = row[e];
        int c = col[e];
        float v = val[e];
        float4 xv = *reinterpret_cast<const float4*>(x + (long)c * DD + k * 4);
        float* dst = g_h + (long)r * DD + k * 4;
        asm volatile("red.global.add.v4.f32 [%0], {%1,%2,%3,%4};"
                     :: "l"(dst), "f"(v * xv.x), "f"(v * xv.y),
                        "f"(v * xv.z), "f"(v * xv.w)
                     : "memory");
    }
}

// ---------------------------------------------------------------------------
// K3: y = h @ W^T + b + x   (W [out,in] in padded smem; 64 nodes per block)
__global__ void k_gemm(const float* __restrict__ x,
                       const float* __restrict__ W,
                       const float* __restrict__ b) {
    __shared__ float Ws[64 * 65];    // padded: bank-conflict-free by (o+in)%32
    __shared__ float hs[4 * 68];     // 4 nodes per chunk, padded
    int t = threadIdx.x;
    for (int i = t; i < 4096; i += 256) {
        int o = i >> 6, in = i & 63;
        Ws[o * 65 + in] = W[i];
    }
    int o  = t & 63;       // output dim
    int nl = t >> 6;       // node-lane 0..3
    float bias = __ldg(&b[o]);
    __syncthreads();

    int base = blockIdx.x * 64;
    for (int chunk = 0; chunk < 16; chunk++) {
        int node = base + chunk * 4 + nl;
        __syncthreads();   // protect hs from previous chunk's readers
        if (node < NN) hs[nl * 68 + o] = g_h[node * DD + o];
        __syncthreads();
        if (node < NN) {
            float acc = bias;
            #pragma unroll
            for (int in = 0; in < 64; in++)
                acc += Ws[o * 65 + in] * hs[nl * 68 + in];
            acc += x[node * DD + o];
            g_y[node * DD + o] = acc;
        }
    }
}

// ---------------------------------------------------------------------------
// K4: per-column sum / sumsq
__global__ void k_stats() {
    __shared__ float ss[64], sq[64];
    int t = threadIdx.x;
    if (t < 64) { ss[t] = 0.f; sq[t] = 0.f; }
    __syncthreads();
    int c  = t & 63;
    int rl = t >> 6;                       // 4 row-lanes per block
    float s = 0.f, q = 0.f;
    for (int r = blockIdx.x * 4 + rl; r < NN; r += gridDim.x * 4) {
        float v = g_y[r * DD + c];
        s += v;
        q += v * v;
    }
    atomicAdd(&ss[c], s);
    atomicAdd(&sq[c], q);
    __syncthreads();
    if (t < 64) {
        atomicAdd(&g_stats[t], ss[t]);
        atomicAdd(&g_stats[64 + t], sq[t]);
    }
}

// ---------------------------------------------------------------------------
// K5: finalize scale/shift (one tiny block)
__global__ void k_finalize(const float* __restrict__ gamma,
                           const float* __restrict__ beta) {
    int c = threadIdx.x;
    if (c < 64) {
        float inv_n = 1.0f / (float)NN;
        float mean = g_stats[c] * inv_n;
        float var  = g_stats[64 + c] * inv_n - mean * mean;
        float sc = gamma[c] * rsqrtf(var + 1e-5f);
        g_scale[c] = sc;
        g_shift[c] = beta[c] - mean * sc;
    }
}

// ---------------------------------------------------------------------------
// K6: out = relu(y * scale + shift)
__global__ void k_norm(float* __restrict__ out, int n4) {
    __shared__ float sc[64], sh[64];
    if (threadIdx.x < 64) {
        sc[threadIdx.x] = g_scale[threadIdx.x];
        sh[threadIdx.x] = g_shift[threadIdx.x];
    }
    __syncthreads();
    const float4* y4 = reinterpret_cast<const float4*>(g_y);
    float4* o4 = reinterpret_cast<float4*>(out);
    for (int i = blockIdx.x * blockDim.x + threadIdx.x; i < n4;
         i += gridDim.x * blockDim.x) {
        int c4 = (i & 15) * 4;   // column of first element (row = 16 float4s)
        float4 v = y4[i];
        v.x = fmaxf(fmaf(v.x, sc[c4 + 0], sh[c4 + 0]), 0.f);
        v.y = fmaxf(fmaf(v.y, sc[c4 + 1], sh[c4 + 1]), 0.f);
        v.z = fmaxf(fmaf(v.z, sc[c4 + 2], sh[c4 + 2]), 0.f);
        v.w = fmaxf(fmaf(v.w, sc[c4 + 3], sh[c4 + 3]), 0.f);
        o4[i] = v;
    }
}

// ---------------------------------------------------------------------------
// inputs (metadata order): x, adj_val, W, b, gamma, beta, adj_row, adj_col
extern "C" void kernel_launch(void* const* d_in, const int* in_sizes, int n_in,
                              void* d_out, int out_size) {
    const float* x       = (const float*)d_in[0];
    const float* adj_val = (const float*)d_in[1];
    const float* W       = (const float*)d_in[2];
    const float* b       = (const float*)d_in[3];
    const float* gamma   = (const float*)d_in[4];
    const float* beta    = (const float*)d_in[5];
    const int*   adj_row = (const int*)d_in[6];
    const int*   adj_col = (const int*)d_in[7];
    float* out = (float*)d_out;
    int E = in_sizes[1];

    int n4 = NN * DD / 4;           // 1.6M float4

    k_zero<<<1184, 256>>>(n4);

    long spmm_threads = (long)E * 16;
    int spmm_blocks = (int)((spmm_threads + 255) / 256);
    k_spmm<<<spmm_blocks, 256>>>(x, adj_val, adj_row, adj_col, E);

    int gemm_blocks = (NN + 63) / 64;
    k_gemm<<<gemm_blocks, 256>>>(x, W, b);

    k_stats<<<512, 256>>>();

    k_finalize<<<1, 64>>>(gamma, beta);

    k_norm<<<1184, 256>>>(out, n4);
}

// round 2
// speedup vs baseline: 1.6624x; 1.6624x over previous
#include <cuda_runtime.h>

#define NN 100000
#define DD 64
#define EMAX 1700000
#define SCAN_CHUNK 1024
#define NSCAN ((NN + SCAN_CHUNK - 1) / SCAN_CHUNK)   // 98

// ----- scratch (device globals; no allocations allowed) -----
__device__ int g_cnt[NN];
__device__ int g_rowptr[NN + 1];
__device__ int g_cursor[NN];
__device__ int g_bsums[NSCAN];
__device__ int g_boff[NSCAN];
__device__ __align__(16) float g_h[NN * DD];
__device__ __align__(16) float g_y[NN * DD];
__device__ int   g_cols[EMAX];
__device__ __align__(16) float g_vals[EMAX];
__device__ float g_stats[128];                 // [0:64) sum, [64:128) sumsq
__device__ float g_scale[DD];
__device__ float g_shift[DD];

// ---------------------------------------------------------------------------
// K1: zero histogram counters + stats
__global__ void k_setup() {
    int gid = blockIdx.x * blockDim.x + threadIdx.x;
    int stride = gridDim.x * blockDim.x;
    for (int i = gid; i < NN; i += stride) g_cnt[i] = 0;
    if (gid < 128) g_stats[gid] = 0.0f;
}

// ---------------------------------------------------------------------------
// K2: histogram of destination rows
__global__ void k_hist(const int* __restrict__ row, int E) {
    int gid = blockIdx.x * blockDim.x + threadIdx.x;
    int stride = gridDim.x * blockDim.x;
    for (int e = gid; e < E; e += stride)
        atomicAdd(&g_cnt[row[e]], 1);
}

// ---------------------------------------------------------------------------
// K3: per-block exclusive scan of g_cnt (1024 elems / block) + block totals
__global__ void k_scan_partial() {
    __shared__ int wsum[8];
    int b = blockIdx.x, t = threadIdx.x;
    int base = b * SCAN_CHUNK + t * 4;
    int v0 = (base + 0 < NN) ? g_cnt[base + 0] : 0;
    int v1 = (base + 1 < NN) ? g_cnt[base + 1] : 0;
    int v2 = (base + 2 < NN) ? g_cnt[base + 2] : 0;
    int v3 = (base + 3 < NN) ? g_cnt[base + 3] : 0;
    int tsum = v0 + v1 + v2 + v3;
    int lane = t & 31, wid = t >> 5;
    int incl = tsum;
    #pragma unroll
    for (int d = 1; d < 32; d <<= 1) {
        int n = __shfl_up_sync(0xffffffffu, incl, d);
        if (lane >= d) incl += n;
    }
    if (lane == 31) wsum[wid] = incl;
    __syncthreads();
    if (wid == 0) {
        int ws = (lane < 8) ? wsum[lane] : 0;
        #pragma unroll
        for (int d = 1; d < 8; d <<= 1) {
            int n = __shfl_up_sync(0xffffffffu, ws, d);
            if (lane >= d) ws += n;
        }
        if (lane < 8) wsum[lane] = ws;       // inclusive over warps
    }
    __syncthreads();
    int woff = (wid > 0) ? wsum[wid - 1] : 0;
    int e0 = woff + incl - tsum;             // exclusive within block
    if (base + 0 < NN) g_rowptr[base + 0] = e0;
    if (base + 1 < NN) g_rowptr[base + 1] = e0 + v0;
    if (base + 2 < NN) g_rowptr[base + 2] = e0 + v0 + v1;
    if (base + 3 < NN) g_rowptr[base + 3] = e0 + v0 + v1 + v2;
    if (t == 0) g_bsums[b] = wsum[7];        // block total
}

// K4: scan of the 98 block totals (single block)
__global__ void k_scan_top() {
    __shared__ int ws2[4];
    int t = threadIdx.x, lane = t & 31, wid = t >> 5;
    int v = (t < NSCAN) ? g_bsums[t] : 0;
    int incl = v;
    #pragma unroll
    for (int d = 1; d < 32; d <<= 1) {
        int n = __shfl_up_sync(0xffffffffu, incl, d);
        if (lane >= d) incl += n;
    }
    if (lane == 31) ws2[wid] = incl;
    __syncthreads();
    if (wid == 0) {
        int w = (lane < 4) ? ws2[lane] : 0;
        #pragma unroll
        for (int d = 1; d < 4; d <<= 1) {
            int n = __shfl_up_sync(0xffffffffu, w, d);
            if (lane >= d) w += n;
        }
        if (lane < 4) ws2[lane] = w;
    }
    __syncthreads();
    int woff = (wid > 0) ? ws2[wid - 1] : 0;
    if (t < NSCAN) g_boff[t] = woff + incl - v;   // exclusive
}

// K5: add block offsets -> global rowptr; init cursor
__global__ void k_scan_add(int E) {
    int gid = blockIdx.x * blockDim.x + threadIdx.x;
    int stride = gridDim.x * blockDim.x;
    for (int i = gid; i < NN; i += stride) {
        int rp = g_rowptr[i] + g_boff[i >> 10];
        g_rowptr[i] = rp;
        g_cursor[i] = rp;
    }
    if (gid == 0) g_rowptr[NN] = E;
}

// ---------------------------------------------------------------------------
// K6: scatter edges into CSR order
__global__ void k_scatter(const int* __restrict__ row,
                          const int* __restrict__ col,
                          const float* __restrict__ val, int E) {
    int gid = blockIdx.x * blockDim.x + threadIdx.x;
    int stride = gridDim.x * blockDim.x;
    for (int e = gid; e < E; e += stride) {
        int r = row[e];
        int pos = atomicAdd(&g_cursor[r], 1);
        g_cols[pos] = col[e];
        g_vals[pos] = val[e];
    }
}

// ---------------------------------------------------------------------------
// K7: CSR SpMM — 16 lanes per row, register accumulation, no atomics
__global__ void k_spmm_csr(const float* __restrict__ x) {
    const float4* x4 = (const float4*)x;
    float4* h4 = (float4*)g_h;
    int t = threadIdx.x;
    int l = t & 15;               // float4 column chunk
    int sub = t >> 4;             // row within block (0..15)
    int r = blockIdx.x * 16 + sub;
    if (r >= NN) return;
    int e = g_rowptr[r];
    int end = g_rowptr[r + 1];
    float4 acc = make_float4(0.f, 0.f, 0.f, 0.f);
    for (; e + 4 <= end; e += 4) {
        int c0 = g_cols[e + 0], c1 = g_cols[e + 1];
        int c2 = g_cols[e + 2], c3 = g_cols[e + 3];
        float v0 = g_vals[e + 0], v1 = g_vals[e + 1];
        float v2 = g_vals[e + 2], v3 = g_vals[e + 3];
        float4 a0 = x4[c0 * 16 + l];
        float4 a1 = x4[c1 * 16 + l];
        float4 a2 = x4[c2 * 16 + l];
        float4 a3 = x4[c3 * 16 + l];
        acc.x = fmaf(v0, a0.x, acc.x); acc.y = fmaf(v0, a0.y, acc.y);
        acc.z = fmaf(v0, a0.z, acc.z); acc.w = fmaf(v0, a0.w, acc.w);
        acc.x = fmaf(v1, a1.x, acc.x); acc.y = fmaf(v1, a1.y, acc.y);
        acc.z = fmaf(v1, a1.z, acc.z); acc.w = fmaf(v1, a1.w, acc.w);
        acc.x = fmaf(v2, a2.x, acc.x); acc.y = fmaf(v2, a2.y, acc.y);
        acc.z = fmaf(v2, a2.z, acc.z); acc.w = fmaf(v2, a2.w, acc.w);
        acc.x = fmaf(v3, a3.x, acc.x); acc.y = fmaf(v3, a3.y, acc.y);
        acc.z = fmaf(v3, a3.z, acc.z); acc.w = fmaf(v3, a3.w, acc.w);
    }
    for (; e < end; e++) {
        int c = g_cols[e];
        float v = g_vals[e];
        float4 a = x4[c * 16 + l];
        acc.x = fmaf(v, a.x, acc.x); acc.y = fmaf(v, a.y, acc.y);
        acc.z = fmaf(v, a.z, acc.z); acc.w = fmaf(v, a.w, acc.w);
    }
    h4[r * 16 + l] = acc;
}

// ---------------------------------------------------------------------------
// K8: y = h @ W^T + b + x, fused BN statistics.
// 64 rows per block; thread (l=t&15, g=t>>4) computes outputs 4l..4l+3 for
// nodes 4g..4g+3 (register-blocked 4x4).
__global__ void k_gemm_stats(const float* __restrict__ x,
                             const float* __restrict__ W,
                             const float* __restrict__ b) {
    __shared__ float wts[64 * 68];   // W transposed: wts[in*68 + o]
    __shared__ float hsm[64 * 68];   // h rows: hsm[rl*68 + in]
    __shared__ float ssm[64], qsm[64];
    int t = threadIdx.x;
    for (int i = t; i < 4096; i += 256) {
        int o = i >> 6, in = i & 63;
        wts[in * 68 + o] = W[i];
    }
    if (t < 64) { ssm[t] = 0.f; qsm[t] = 0.f; }

    int l = t & 15, g = t >> 4;
    int row0 = blockIdx.x * 64;

    const float4* h4g = (const float4*)g_h;
    float4* hsm4 = (float4*)hsm;               // row stride = 17 float4
    for (int i = t; i < 1024; i += 256) {
        int rl = i >> 4, c4 = i & 15;
        int r = row0 + rl;
        float4 hv = (r < NN) ? h4g[r * 16 + c4] : make_float4(0.f, 0.f, 0.f, 0.f);
        hsm4[rl * 17 + c4] = hv;
    }
    __syncthreads();

    float4 bias = ((const float4*)b)[l];
    float4 acc0 = bias, acc1 = bias, acc2 = bias, acc3 = bias;
    const float4* wts4 = (const float4*)wts;   // row stride = 17 float4
    int hb = (4 * g) * 68;
    #pragma unroll 8
    for (int in = 0; in < 64; in++) {
        float4 w4 = wts4[in * 17 + l];
        float h0 = hsm[hb + in];
        float h1 = hsm[hb + 68 + in];
        float h2 = hsm[hb + 136 + in];
        float h3 = hsm[hb + 204 + in];
        acc0.x = fmaf(w4.x, h0, acc0.x); acc0.y = fmaf(w4.y, h0, acc0.y);
        acc0.z = fmaf(w4.z, h0, acc0.z); acc0.w = fmaf(w4.w, h0, acc0.w);
        acc1.x = fmaf(w4.x, h1, acc1.x); acc1.y = fmaf(w4.y, h1, acc1.y);
        acc1.z = fmaf(w4.z, h1, acc1.z); acc1.w = fmaf(w4.w, h1, acc1.w);
        acc2.x = fmaf(w4.x, h2, acc2.x); acc2.y = fmaf(w4.y, h2, acc2.y);
        acc2.z = fmaf(w4.z, h2, acc2.z); acc2.w = fmaf(w4.w, h2, acc2.w);
        acc3.x = fmaf(w4.x, h3, acc3.x); acc3.y = fmaf(w4.y, h3, acc3.y);
        acc3.z = fmaf(w4.z, h3, acc3.z); acc3.w = fmaf(w4.w, h3, acc3.w);
    }

    const float4* x4g = (const float4*)x;
    float4* y4 = (float4*)g_y;
    float4 s4 = make_float4(0.f, 0.f, 0.f, 0.f);
    float4 q4 = make_float4(0.f, 0.f, 0.f, 0.f);
    int r0 = row0 + 4 * g;
    float4 accs[4] = {acc0, acc1, acc2, acc3};
    #pragma unroll
    for (int ni = 0; ni < 4; ni++) {
        int r = r0 + ni;
        if (r < NN) {
            float4 xv = x4g[r * 16 + l];
            float4 a = accs[ni];
            a.x += xv.x; a.y += xv.y; a.z += xv.z; a.w += xv.w;
            y4[r * 16 + l] = a;
            s4.x += a.x; s4.y += a.y; s4.z += a.z; s4.w += a.w;
            q4.x = fmaf(a.x, a.x, q4.x); q4.y = fmaf(a.y, a.y, q4.y);
            q4.z = fmaf(a.z, a.z, q4.z); q4.w = fmaf(a.w, a.w, q4.w);
        }
    }
    atomicAdd(&ssm[l * 4 + 0], s4.x); atomicAdd(&ssm[l * 4 + 1], s4.y);
    atomicAdd(&ssm[l * 4 + 2], s4.z); atomicAdd(&ssm[l * 4 + 3], s4.w);
    atomicAdd(&qsm[l * 4 + 0], q4.x); atomicAdd(&qsm[l * 4 + 1], q4.y);
    atomicAdd(&qsm[l * 4 + 2], q4.z); atomicAdd(&qsm[l * 4 + 3], q4.w);
    __syncthreads();
    if (t < 64) {
        atomicAdd(&g_stats[t], ssm[t]);
        atomicAdd(&g_stats[64 + t], qsm[t]);
    }
}

// ---------------------------------------------------------------------------
// K9: finalize BN scale/shift
__global__ void k_finalize(const float* __restrict__ gamma,
                           const float* __restrict__ beta) {
    int c = threadIdx.x;
    if (c < 64) {
        float inv_n = 1.0f / (float)NN;
        float mean = g_stats[c] * inv_n;
        float var  = g_stats[64 + c] * inv_n - mean * mean;
        float sc = gamma[c] * rsqrtf(var + 1e-5f);
        g_scale[c] = sc;
        g_shift[c] = beta[c] - mean * sc;
    }
}

// ---------------------------------------------------------------------------
// K10: out = relu(y * scale + shift)
__global__ void k_norm(float* __restrict__ out, int n4) {
    __shared__ float sc[64], sh[64];
    if (threadIdx.x < 64) {
        sc[threadIdx.x] = g_scale[threadIdx.x];
        sh[threadIdx.x] = g_shift[threadIdx.x];
    }
    __syncthreads();
    const float4* y4 = reinterpret_cast<const float4*>(g_y);
    float4* o4 = reinterpret_cast<float4*>(out);
    for (int i = blockIdx.x * blockDim.x + threadIdx.x; i < n4;
         i += gridDim.x * blockDim.x) {
        int c4 = (i & 15) * 4;
        float4 v = y4[i];
        v.x = fmaxf(fmaf(v.x, sc[c4 + 0], sh[c4 + 0]), 0.f);
        v.y = fmaxf(fmaf(v.y, sc[c4 + 1], sh[c4 + 1]), 0.f);
        v.z = fmaxf(fmaf(v.z, sc[c4 + 2], sh[c4 + 2]), 0.f);
        v.w = fmaxf(fmaf(v.w, sc[c4 + 3], sh[c4 + 3]), 0.f);
        o4[i] = v;
    }
}

// ---------------------------------------------------------------------------
// inputs (metadata order): x, adj_val, W, b, gamma, beta, adj_row, adj_col
extern "C" void kernel_launch(void* const* d_in, const int* in_sizes, int n_in,
                              void* d_out, int out_size) {
    const float* x       = (const float*)d_in[0];
    const float* adj_val = (const float*)d_in[1];
    const float* W       = (const float*)d_in[2];
    const float* b       = (const float*)d_in[3];
    const float* gamma   = (const float*)d_in[4];
    const float* beta    = (const float*)d_in[5];
    const int*   adj_row = (const int*)d_in[6];
    const int*   adj_col = (const int*)d_in[7];
    float* out = (float*)d_out;
    int E = in_sizes[1];

    int n4 = NN * DD / 4;

    k_setup<<<392, 256>>>();
    k_hist<<<1184, 256>>>(adj_row, E);
    k_scan_partial<<<NSCAN, 256>>>();
    k_scan_top<<<1, 128>>>();
    k_scan_add<<<392, 256>>>(E);
    k_scatter<<<1184, 256>>>(adj_row, adj_col, adj_val, E);
    k_spmm_csr<<<(NN + 15) / 16, 256>>>(x);
    k_gemm_stats<<<(NN + 63) / 64, 256>>>(x, W, b);
    k_finalize<<<1, 64>>>(gamma, beta);
    k_norm<<<1184, 256>>>(out, n4);
}

// round 3
// speedup vs baseline: 1.7176x; 1.0332x over previous
#include <cuda_runtime.h>

#define NN 100000
#define DD 64
#define EMAX 1700000
#define SCAN_CHUNK 1024
#define NSCAN ((NN + SCAN_CHUNK - 1) / SCAN_CHUNK)   // 98

// ----- scratch (device globals; no allocations allowed) -----
__device__ int g_cnt[NN];
__device__ int g_rowptr[NN + 1];
__device__ int g_cursor[NN];
__device__ int g_scan_status[NSCAN];   // 0=empty 1=aggregate 2=prefix
__device__ int g_scan_val[NSCAN];
__device__ int g_scan_incl[NSCAN];
__device__ __align__(16) float g_h[NN * DD];
__device__ __align__(16) float g_y[NN * DD];
__device__ __align__(16) int2 g_edge[EMAX];    // packed (col, val-bits)
__device__ float g_stats[128];                 // [0:64) sum, [64:128) sumsq
__device__ float g_scale[DD];
__device__ float g_shift[DD];

// ---------------------------------------------------------------------------
// K1: zero histogram counters + stats + scan status
__global__ void k_setup() {
    int gid = blockIdx.x * blockDim.x + threadIdx.x;
    int stride = gridDim.x * blockDim.x;
    for (int i = gid; i < NN; i += stride) g_cnt[i] = 0;
    if (gid < 128) g_stats[gid] = 0.0f;
    if (gid < NSCAN) g_scan_status[gid] = 0;
}

// ---------------------------------------------------------------------------
// K2: histogram of destination rows
__global__ void k_hist(const int* __restrict__ row, int E) {
    int gid = blockIdx.x * blockDim.x + threadIdx.x;
    int stride = gridDim.x * blockDim.x;
    for (int e = gid; e < E; e += stride)
        atomicAdd(&g_cnt[row[e]], 1);
}

// ---------------------------------------------------------------------------
// K3: single-pass exclusive scan (decoupled lookback), writes rowptr + cursor
__global__ void k_scan(int E) {
    __shared__ int wsum[8];
    __shared__ int s_excl;
    int b = blockIdx.x, t = threadIdx.x;
    int base = b * SCAN_CHUNK + t * 4;
    int v0 = (base + 0 < NN) ? g_cnt[base + 0] : 0;
    int v1 = (base + 1 < NN) ? g_cnt[base + 1] : 0;
    int v2 = (base + 2 < NN) ? g_cnt[base + 2] : 0;
    int v3 = (base + 3 < NN) ? g_cnt[base + 3] : 0;
    int tsum = v0 + v1 + v2 + v3;
    int lane = t & 31, wid = t >> 5;
    int incl = tsum;
    #pragma unroll
    for (int d = 1; d < 32; d <<= 1) {
        int n = __shfl_up_sync(0xffffffffu, incl, d);
        if (lane >= d) incl += n;
    }
    if (lane == 31) wsum[wid] = incl;
    __syncthreads();
    if (wid == 0) {
        int ws = (lane < 8) ? wsum[lane] : 0;
        #pragma unroll
        for (int d = 1; d < 8; d <<= 1) {
            int n = __shfl_up_sync(0xffffffffu, ws, d);
            if (lane >= d) ws += n;
        }
        if (lane < 8) wsum[lane] = ws;       // inclusive over warps
    }
    __syncthreads();
    int total = wsum[7];

    // publish aggregate
    if (t == 0) {
        g_scan_val[b] = total;
        __threadfence();
        atomicExch(&g_scan_status[b], 1);
    }

    // warp 0: parallel lookback
    if (wid == 0) {
        int sum = 0;
        int look = b;
        while (look > 0) {
            int idx = look - 32 + lane;           // may be < 0
            int st;
            do {
                st = (idx >= 0) ? ((volatile int*)g_scan_status)[idx] : 2;
            } while (__any_sync(0xffffffffu, st == 0));
            __threadfence();
            unsigned pref2 = __ballot_sync(0xffffffffu, (st == 2) && (idx >= 0));
            int contrib = 0;
            if (pref2) {
                int hi = 31 - __clz(pref2);       // highest lane with a prefix
                if (idx >= 0) {
                    if (lane > hi)       contrib = ((volatile int*)g_scan_val)[idx];
                    else if (lane == hi) contrib = ((volatile int*)g_scan_incl)[idx];
                }
            } else {
                if (idx >= 0) contrib = ((volatile int*)g_scan_val)[idx];
            }
            #pragma unroll
            for (int d = 16; d; d >>= 1)
                contrib += __shfl_xor_sync(0xffffffffu, contrib, d);
            sum += contrib;
            if (pref2) break;
            look -= 32;
        }
        if (lane == 0) {
            s_excl = sum;
            g_scan_incl[b] = sum + total;
            __threadfence();
            atomicExch(&g_scan_status[b], 2);
        }
    }
    __syncthreads();

    int off = s_excl;
    int woff = (wid > 0) ? wsum[wid - 1] : 0;
    int e0 = off + woff + incl - tsum;            // global exclusive
    if (base + 0 < NN) { g_rowptr[base + 0] = e0;               g_cursor[base + 0] = e0; }
    if (base + 1 < NN) { g_rowptr[base + 1] = e0 + v0;          g_cursor[base + 1] = e0 + v0; }
    if (base + 2 < NN) { g_rowptr[base + 2] = e0 + v0 + v1;     g_cursor[base + 2] = e0 + v0 + v1; }
    if (base + 3 < NN) { g_rowptr[base + 3] = e0 + v0 + v1 + v2; g_cursor[base + 3] = e0 + v0 + v1 + v2; }
    if (b == 0 && t == 0) g_rowptr[NN] = E;
}

// ---------------------------------------------------------------------------
// K4: scatter edges into CSR order (packed 8-byte payload)
__global__ void k_scatter(const int* __restrict__ row,
                          const int* __restrict__ col,
                          const float* __restrict__ val, int E) {
    int gid = blockIdx.x * blockDim.x + threadIdx.x;
    int stride = gridDim.x * blockDim.x;
    for (int e = gid; e < E; e += stride) {
        int r = row[e];
        int pos = atomicAdd(&g_cursor[r], 1);
        g_edge[pos] = make_int2(col[e], __float_as_int(val[e]));
    }
}

// ---------------------------------------------------------------------------
// K5: CSR SpMM — 16 lanes per row, register accumulation, no atomics
__global__ void k_spmm_csr(const float* __restrict__ x) {
    const float4* x4 = (const float4*)x;
    float4* h4 = (float4*)g_h;
    int t = threadIdx.x;
    int l = t & 15;               // float4 column chunk
    int sub = t >> 4;             // row within block (0..15)
    int r = blockIdx.x * 16 + sub;
    if (r >= NN) return;
    int e = g_rowptr[r];
    int end = g_rowptr[r + 1];
    float4 acc = make_float4(0.f, 0.f, 0.f, 0.f);
    for (; e + 4 <= end; e += 4) {
        int2 e0 = g_edge[e + 0], e1 = g_edge[e + 1];
        int2 e2 = g_edge[e + 2], e3 = g_edge[e + 3];
        float v0 = __int_as_float(e0.y), v1 = __int_as_float(e1.y);
        float v2 = __int_as_float(e2.y), v3 = __int_as_float(e3.y);
        float4 a0 = x4[e0.x * 16 + l];
        float4 a1 = x4[e1.x * 16 + l];
        float4 a2 = x4[e2.x * 16 + l];
        float4 a3 = x4[e3.x * 16 + l];
        acc.x = fmaf(v0, a0.x, acc.x); acc.y = fmaf(v0, a0.y, acc.y);
        acc.z = fmaf(v0, a0.z, acc.z); acc.w = fmaf(v0, a0.w, acc.w);
        acc.x = fmaf(v1, a1.x, acc.x); acc.y = fmaf(v1, a1.y, acc.y);
        acc.z = fmaf(v1, a1.z, acc.z); acc.w = fmaf(v1, a1.w, acc.w);
        acc.x = fmaf(v2, a2.x, acc.x); acc.y = fmaf(v2, a2.y, acc.y);
        acc.z = fmaf(v2, a2.z, acc.z); acc.w = fmaf(v2, a2.w, acc.w);
        acc.x = fmaf(v3, a3.x, acc.x); acc.y = fmaf(v3, a3.y, acc.y);
        acc.z = fmaf(v3, a3.z, acc.z); acc.w = fmaf(v3, a3.w, acc.w);
    }
    for (; e < end; e++) {
        int2 ed = g_edge[e];
        float v = __int_as_float(ed.y);
        float4 a = x4[ed.x * 16 + l];
        acc.x = fmaf(v, a.x, acc.x); acc.y = fmaf(v, a.y, acc.y);
        acc.z = fmaf(v, a.z, acc.z); acc.w = fmaf(v, a.w, acc.w);
    }
    h4[r * 16 + l] = acc;
}

// ---------------------------------------------------------------------------
// K6: y = h @ W^T + b + x, fused BN statistics (register-blocked 4x4)
__global__ void k_gemm_stats(const float* __restrict__ x,
                             const float* __restrict__ W,
                             const float* __restrict__ b) {
    __shared__ float wts[64 * 68];   // W transposed: wts[in*68 + o]
    __shared__ float hsm[64 * 68];   // h rows: hsm[rl*68 + in]
    __shared__ float ssm[64], qsm[64];
    int t = threadIdx.x;
    for (int i = t; i < 4096; i += 256) {
        int o = i >> 6, in = i & 63;
        wts[in * 68 + o] = W[i];
    }
    if (t < 64) { ssm[t] = 0.f; qsm[t] = 0.f; }

    int l = t & 15, g = t >> 4;
    int row0 = blockIdx.x * 64;

    const float4* h4g = (const float4*)g_h;
    float4* hsm4 = (float4*)hsm;               // row stride = 17 float4
    for (int i = t; i < 1024; i += 256) {
        int rl = i >> 4, c4 = i & 15;
        int r = row0 + rl;
        float4 hv = (r < NN) ? h4g[r * 16 + c4] : make_float4(0.f, 0.f, 0.f, 0.f);
        hsm4[rl * 17 + c4] = hv;
    }
    __syncthreads();

    float4 bias = ((const float4*)b)[l];
    float4 acc0 = bias, acc1 = bias, acc2 = bias, acc3 = bias;
    const float4* wts4 = (const float4*)wts;   // row stride = 17 float4
    int hb = (4 * g) * 68;
    #pragma unroll 8
    for (int in = 0; in < 64; in++) {
        float4 w4 = wts4[in * 17 + l];
        float h0 = hsm[hb + in];
        float h1 = hsm[hb + 68 + in];
        float h2 = hsm[hb + 136 + in];
        float h3 = hsm[hb + 204 + in];
        acc0.x = fmaf(w4.x, h0, acc0.x); acc0.y = fmaf(w4.y, h0, acc0.y);
        acc0.z = fmaf(w4.z, h0, acc0.z); acc0.w = fmaf(w4.w, h0, acc0.w);
        acc1.x = fmaf(w4.x, h1, acc1.x); acc1.y = fmaf(w4.y, h1, acc1.y);
        acc1.z = fmaf(w4.z, h1, acc1.z); acc1.w = fmaf(w4.w, h1, acc1.w);
        acc2.x = fmaf(w4.x, h2, acc2.x); acc2.y = fmaf(w4.y, h2, acc2.y);
        acc2.z = fmaf(w4.z, h2, acc2.z); acc2.w = fmaf(w4.w, h2, acc2.w);
        acc3.x = fmaf(w4.x, h3, acc3.x); acc3.y = fmaf(w4.y, h3, acc3.y);
        acc3.z = fmaf(w4.z, h3, acc3.z); acc3.w = fmaf(w4.w, h3, acc3.w);
    }

    const float4* x4g = (const float4*)x;
    float4* y4 = (float4*)g_y;
    float4 s4 = make_float4(0.f, 0.f, 0.f, 0.f);
    float4 q4 = make_float4(0.f, 0.f, 0.f, 0.f);
    int r0 = row0 + 4 * g;
    float4 accs[4] = {acc0, acc1, acc2, acc3};
    #pragma unroll
    for (int ni = 0; ni < 4; ni++) {
        int r = r0 + ni;
        if (r < NN) {
            float4 xv = x4g[r * 16 + l];
            float4 a = accs[ni];
            a.x += xv.x; a.y += xv.y; a.z += xv.z; a.w += xv.w;
            y4[r * 16 + l] = a;
            s4.x += a.x; s4.y += a.y; s4.z += a.z; s4.w += a.w;
            q4.x = fmaf(a.x, a.x, q4.x); q4.y = fmaf(a.y, a.y, q4.y);
            q4.z = fmaf(a.z, a.z, q4.z); q4.w = fmaf(a.w, a.w, q4.w);
        }
    }
    atomicAdd(&ssm[l * 4 + 0], s4.x); atomicAdd(&ssm[l * 4 + 1], s4.y);
    atomicAdd(&ssm[l * 4 + 2], s4.z); atomicAdd(&ssm[l * 4 + 3], s4.w);
    atomicAdd(&qsm[l * 4 + 0], q4.x); atomicAdd(&qsm[l * 4 + 1], q4.y);
    atomicAdd(&qsm[l * 4 + 2], q4.z); atomicAdd(&qsm[l * 4 + 3], q4.w);
    __syncthreads();
    if (t < 64) {
        atomicAdd(&g_stats[t], ssm[t]);
        atomicAdd(&g_stats[64 + t], qsm[t]);
    }
}

// ---------------------------------------------------------------------------
// K7: out = relu(y * scale + shift); scale/shift derived per-block (fused finalize)
__global__ void k_norm(float* __restrict__ out,
                       const float* __restrict__ gamma,
                       const float* __restrict__ beta, int n4) {
    __shared__ float sc[64], sh[64];
    int t = threadIdx.x;
    if (t < 64) {
        float inv_n = 1.0f / (float)NN;
        float mean = g_stats[t] * inv_n;
        float var  = g_stats[64 + t] * inv_n - mean * mean;
        float s = gamma[t] * rsqrtf(var + 1e-5f);
        sc[t] = s;
        sh[t] = beta[t] - mean * s;
    }
    __syncthreads();
    const float4* y4 = reinterpret_cast<const float4*>(g_y);
    float4* o4 = reinterpret_cast<float4*>(out);
    for (int i = blockIdx.x * blockDim.x + t; i < n4;
         i += gridDim.x * blockDim.x) {
        int c4 = (i & 15) * 4;
        float4 v = y4[i];
        v.x = fmaxf(fmaf(v.x, sc[c4 + 0], sh[c4 + 0]), 0.f);
        v.y = fmaxf(fmaf(v.y, sc[c4 + 1], sh[c4 + 1]), 0.f);
        v.z = fmaxf(fmaf(v.z, sc[c4 + 2], sh[c4 + 2]), 0.f);
        v.w = fmaxf(fmaf(v.w, sc[c4 + 3], sh[c4 + 3]), 0.f);
        o4[i] = v;
    }
}

// ---------------------------------------------------------------------------
// inputs (metadata order): x, adj_val, W, b, gamma, beta, adj_row, adj_col
extern "C" void kernel_launch(void* const* d_in, const int* in_sizes, int n_in,
                              void* d_out, int out_size) {
    const float* x       = (const float*)d_in[0];
    const float* adj_val = (const float*)d_in[1];
    const float* W       = (const float*)d_in[2];
    const float* b       = (const float*)d_in[3];
    const float* gamma   = (const float*)d_in[4];
    const float* beta    = (const float*)d_in[5];
    const int*   adj_row = (const int*)d_in[6];
    const int*   adj_col = (const int*)d_in[7];
    float* out = (float*)d_out;
    int E = in_sizes[1];

    int n4 = NN * DD / 4;

    k_setup<<<392, 256>>>();
    k_hist<<<1184, 256>>>(adj_row, E);
    k_scan<<<NSCAN, 256>>>(E);
    k_scatter<<<1184, 256>>>(adj_row, adj_col, adj_val, E);
    k_spmm_csr<<<(NN + 15) / 16, 256>>>(x);
    k_gemm_stats<<<(NN + 63) / 64, 256>>>(x, W, b);
    k_norm<<<1184, 256>>>(out, gamma, beta, n4);
}

// round 4
// speedup vs baseline: 1.7932x; 1.0441x over previous
#include <cuda_runtime.h>

#define NN 100000
#define DD 64
#define EMAX 1700000
#define SCAN_CHUNK 1024
#define NSCAN ((NN + SCAN_CHUNK - 1) / SCAN_CHUNK)   // 98

// ----- scratch (device globals; no allocations allowed) -----
// g_cnt is zero at process start (BSS) and k_scan re-zeroes it each call,
// so the zero-invariant holds across graph replays.
__device__ int g_cnt[NN];
__device__ int g_rowptr[NN + 1];
__device__ int g_rank[EMAX];           // rank of edge within its row
__device__ int g_scan_status[NSCAN];   // 0=empty 1=aggregate 2=prefix
__device__ int g_scan_val[NSCAN];
__device__ int g_scan_incl[NSCAN];
__device__ __align__(16) float g_h[NN * DD];
__device__ __align__(16) float g_y[NN * DD];
__device__ __align__(16) int2 g_edge[EMAX];    // packed (col, val-bits)
__device__ float g_stats[128];                 // [0:64) sum, [64:128) sumsq

// ---------------------------------------------------------------------------
// K1: histogram of destination rows; atomic return value = rank within row.
// Also zeroes the small control arrays (stats, scan status) for this call.
__global__ void k_hist(const int* __restrict__ row, int E) {
    int gid = blockIdx.x * blockDim.x + threadIdx.x;
    int stride = gridDim.x * blockDim.x;
    if (gid < 128) g_stats[gid] = 0.0f;
    if (gid < NSCAN) g_scan_status[gid] = 0;
    for (int e = gid; e < E; e += stride)
        g_rank[e] = atomicAdd(&g_cnt[row[e]], 1);
}

// ---------------------------------------------------------------------------
// K2: single-pass exclusive scan (decoupled lookback) -> rowptr.
// Re-zeroes g_cnt after consuming it (maintains cross-call invariant).
__global__ void k_scan(int E) {
    __shared__ int wsum[8];
    __shared__ int s_excl;
    int b = blockIdx.x, t = threadIdx.x;
    int base = b * SCAN_CHUNK + t * 4;
    int v0 = (base + 0 < NN) ? g_cnt[base + 0] : 0;
    int v1 = (base + 1 < NN) ? g_cnt[base + 1] : 0;
    int v2 = (base + 2 < NN) ? g_cnt[base + 2] : 0;
    int v3 = (base + 3 < NN) ? g_cnt[base + 3] : 0;
    if (base + 0 < NN) g_cnt[base + 0] = 0;
    if (base + 1 < NN) g_cnt[base + 1] = 0;
    if (base + 2 < NN) g_cnt[base + 2] = 0;
    if (base + 3 < NN) g_cnt[base + 3] = 0;
    int tsum = v0 + v1 + v2 + v3;
    int lane = t & 31, wid = t >> 5;
    int incl = tsum;
    #pragma unroll
    for (int d = 1; d < 32; d <<= 1) {
        int n = __shfl_up_sync(0xffffffffu, incl, d);
        if (lane >= d) incl += n;
    }
    if (lane == 31) wsum[wid] = incl;
    __syncthreads();
    if (wid == 0) {
        int ws = (lane < 8) ? wsum[lane] : 0;
        #pragma unroll
        for (int d = 1; d < 8; d <<= 1) {
            int n = __shfl_up_sync(0xffffffffu, ws, d);
            if (lane >= d) ws += n;
        }
        if (lane < 8) wsum[lane] = ws;       // inclusive over warps
    }
    __syncthreads();
    int total = wsum[7];

    // publish aggregate
    if (t == 0) {
        g_scan_val[b] = total;
        __threadfence();
        atomicExch(&g_scan_status[b], 1);
    }

    // warp 0: parallel lookback
    if (wid == 0) {
        int sum = 0;
        int look = b;
        while (look > 0) {
            int idx = look - 32 + lane;           // may be < 0
            int st;
            do {
                st = (idx >= 0) ? ((volatile int*)g_scan_status)[idx] : 2;
            } while (__any_sync(0xffffffffu, st == 0));
            __threadfence();
            unsigned pref2 = __ballot_sync(0xffffffffu, (st == 2) && (idx >= 0));
            int contrib = 0;
            if (pref2) {
                int hi = 31 - __clz(pref2);       // highest lane with a prefix
                if (idx >= 0) {
                    if (lane > hi)       contrib = ((volatile int*)g_scan_val)[idx];
                    else if (lane == hi) contrib = ((volatile int*)g_scan_incl)[idx];
                }
            } else {
                if (idx >= 0) contrib = ((volatile int*)g_scan_val)[idx];
            }
            #pragma unroll
            for (int d = 16; d; d >>= 1)
                contrib += __shfl_xor_sync(0xffffffffu, contrib, d);
            sum += contrib;
            if (pref2) break;
            look -= 32;
        }
        if (lane == 0) {
            s_excl = sum;
            g_scan_incl[b] = sum + total;
            __threadfence();
            atomicExch(&g_scan_status[b], 2);
        }
    }
    __syncthreads();

    int off = s_excl;
    int woff = (wid > 0) ? wsum[wid - 1] : 0;
    int e0 = off + woff + incl - tsum;            // global exclusive
    if (base + 0 < NN) g_rowptr[base + 0] = e0;
    if (base + 1 < NN) g_rowptr[base + 1] = e0 + v0;
    if (base + 2 < NN) g_rowptr[base + 2] = e0 + v0 + v1;
    if (base + 3 < NN) g_rowptr[base + 3] = e0 + v0 + v1 + v2;
    if (b == 0 && t == 0) g_rowptr[NN] = E;
}

// ---------------------------------------------------------------------------
// K3: atomic-free scatter: pos = rowptr[row] + rank  (pure function)
__global__ void k_scatter(const int* __restrict__ row,
                          const int* __restrict__ col,
                          const float* __restrict__ val, int E) {
    int gid = blockIdx.x * blockDim.x + threadIdx.x;
    int stride = gridDim.x * blockDim.x;
    for (int e = gid; e < E; e += stride) {
        int r = row[e];
        int pos = g_rowptr[r] + g_rank[e];
        g_edge[pos] = make_int2(col[e], __float_as_int(val[e]));
    }
}

// ---------------------------------------------------------------------------
// K4: CSR SpMM — 16 lanes per row, register accumulation, no atomics
__global__ void k_spmm_csr(const float* __restrict__ x) {
    const float4* x4 = (const float4*)x;
    float4* h4 = (float4*)g_h;
    int t = threadIdx.x;
    int l = t & 15;               // float4 column chunk
    int sub = t >> 4;             // row within block (0..15)
    int r = blockIdx.x * 16 + sub;
    if (r >= NN) return;
    int e = g_rowptr[r];
    int end = g_rowptr[r + 1];
    float4 acc = make_float4(0.f, 0.f, 0.f, 0.f);
    for (; e + 4 <= end; e += 4) {
        int2 e0 = g_edge[e + 0], e1 = g_edge[e + 1];
        int2 e2 = g_edge[e + 2], e3 = g_edge[e + 3];
        float v0 = __int_as_float(e0.y), v1 = __int_as_float(e1.y);
        float v2 = __int_as_float(e2.y), v3 = __int_as_float(e3.y);
        float4 a0 = x4[e0.x * 16 + l];
        float4 a1 = x4[e1.x * 16 + l];
        float4 a2 = x4[e2.x * 16 + l];
        float4 a3 = x4[e3.x * 16 + l];
        acc.x = fmaf(v0, a0.x, acc.x); acc.y = fmaf(v0, a0.y, acc.y);
        acc.z = fmaf(v0, a0.z, acc.z); acc.w = fmaf(v0, a0.w, acc.w);
        acc.x = fmaf(v1, a1.x, acc.x); acc.y = fmaf(v1, a1.y, acc.y);
        acc.z = fmaf(v1, a1.z, acc.z); acc.w = fmaf(v1, a1.w, acc.w);
        acc.x = fmaf(v2, a2.x, acc.x); acc.y = fmaf(v2, a2.y, acc.y);
        acc.z = fmaf(v2, a2.z, acc.z); acc.w = fmaf(v2, a2.w, acc.w);
        acc.x = fmaf(v3, a3.x, acc.x); acc.y = fmaf(v3, a3.y, acc.y);
        acc.z = fmaf(v3, a3.z, acc.z); acc.w = fmaf(v3, a3.w, acc.w);
    }
    for (; e < end; e++) {
        int2 ed = g_edge[e];
        float v = __int_as_float(ed.y);
        float4 a = x4[ed.x * 16 + l];
        acc.x = fmaf(v, a.x, acc.x); acc.y = fmaf(v, a.y, acc.y);
        acc.z = fmaf(v, a.z, acc.z); acc.w = fmaf(v, a.w, acc.w);
    }
    h4[r * 16 + l] = acc;
}

// ---------------------------------------------------------------------------
// K5: y = h @ W^T + b + x, fused BN statistics (register-blocked 4x4)
__global__ void k_gemm_stats(const float* __restrict__ x,
                             const float* __restrict__ W,
                             const float* __restrict__ b) {
    __shared__ float wts[64 * 68];   // W transposed: wts[in*68 + o]
    __shared__ float hsm[64 * 68];   // h rows: hsm[rl*68 + in]
    __shared__ float ssm[64], qsm[64];
    int t = threadIdx.x;
    for (int i = t; i < 4096; i += 256) {
        int o = i >> 6, in = i & 63;
        wts[in * 68 + o] = W[i];
    }
    if (t < 64) { ssm[t] = 0.f; qsm[t] = 0.f; }

    int l = t & 15, g = t >> 4;
    int row0 = blockIdx.x * 64;

    const float4* h4g = (const float4*)g_h;
    float4* hsm4 = (float4*)hsm;               // row stride = 17 float4
    for (int i = t; i < 1024; i += 256) {
        int rl = i >> 4, c4 = i & 15;
        int r = row0 + rl;
        float4 hv = (r < NN) ? h4g[r * 16 + c4] : make_float4(0.f, 0.f, 0.f, 0.f);
        hsm4[rl * 17 + c4] = hv;
    }
    __syncthreads();

    float4 bias = ((const float4*)b)[l];
    float4 acc0 = bias, acc1 = bias, acc2 = bias, acc3 = bias;
    const float4* wts4 = (const float4*)wts;   // row stride = 17 float4
    int hb = (4 * g) * 68;
    #pragma unroll 8
    for (int in = 0; in < 64; in++) {
        float4 w4 = wts4[in * 17 + l];
        float h0 = hsm[hb + in];
        float h1 = hsm[hb + 68 + in];
        float h2 = hsm[hb + 136 + in];
        float h3 = hsm[hb + 204 + in];
        acc0.x = fmaf(w4.x, h0, acc0.x); acc0.y = fmaf(w4.y, h0, acc0.y);
        acc0.z = fmaf(w4.z, h0, acc0.z); acc0.w = fmaf(w4.w, h0, acc0.w);
        acc1.x = fmaf(w4.x, h1, acc1.x); acc1.y = fmaf(w4.y, h1, acc1.y);
        acc1.z = fmaf(w4.z, h1, acc1.z); acc1.w = fmaf(w4.w, h1, acc1.w);
        acc2.x = fmaf(w4.x, h2, acc2.x); acc2.y = fmaf(w4.y, h2, acc2.y);
        acc2.z = fmaf(w4.z, h2, acc2.z); acc2.w = fmaf(w4.w, h2, acc2.w);
        acc3.x = fmaf(w4.x, h3, acc3.x); acc3.y = fmaf(w4.y, h3, acc3.y);
        acc3.z = fmaf(w4.z, h3, acc3.z); acc3.w = fmaf(w4.w, h3, acc3.w);
    }

    const float4* x4g = (const float4*)x;
    float4* y4 = (float4*)g_y;
    float4 s4 = make_float4(0.f, 0.f, 0.f, 0.f);
    float4 q4 = make_float4(0.f, 0.f, 0.f, 0.f);
    int r0 = row0 + 4 * g;
    float4 accs[4] = {acc0, acc1, acc2, acc3};
    #pragma unroll
    for (int ni = 0; ni < 4; ni++) {
        int r = r0 + ni;
        if (r < NN) {
            float4 xv = x4g[r * 16 + l];
            float4 a = accs[ni];
            a.x += xv.x; a.y += xv.y; a.z += xv.z; a.w += xv.w;
            y4[r * 16 + l] = a;
            s4.x += a.x; s4.y += a.y; s4.z += a.z; s4.w += a.w;
            q4.x = fmaf(a.x, a.x, q4.x); q4.y = fmaf(a.y, a.y, q4.y);
            q4.z = fmaf(a.z, a.z, q4.z); q4.w = fmaf(a.w, a.w, q4.w);
        }
    }
    atomicAdd(&ssm[l * 4 + 0], s4.x); atomicAdd(&ssm[l * 4 + 1], s4.y);
    atomicAdd(&ssm[l * 4 + 2], s4.z); atomicAdd(&ssm[l * 4 + 3], s4.w);
    atomicAdd(&qsm[l * 4 + 0], q4.x); atomicAdd(&qsm[l * 4 + 1], q4.y);
    atomicAdd(&qsm[l * 4 + 2], q4.z); atomicAdd(&qsm[l * 4 + 3], q4.w);
    __syncthreads();
    if (t < 64) {
        atomicAdd(&g_stats[t], ssm[t]);
        atomicAdd(&g_stats[64 + t], qsm[t]);
    }
}

// ---------------------------------------------------------------------------
// K6: out = relu(y * scale + shift); scale/shift derived per-block
__global__ void k_norm(float* __restrict__ out,
                       const float* __restrict__ gamma,
                       const float* __restrict__ beta, int n4) {
    __shared__ float sc[64], sh[64];
    int t = threadIdx.x;
    if (t < 64) {
        float inv_n = 1.0f / (float)NN;
        float mean = g_stats[t] * inv_n;
        float var  = g_stats[64 + t] * inv_n - mean * mean;
        float s = gamma[t] * rsqrtf(var + 1e-5f);
        sc[t] = s;
        sh[t] = beta[t] - mean * s;
    }
    __syncthreads();
    const float4* y4 = reinterpret_cast<const float4*>(g_y);
    float4* o4 = reinterpret_cast<float4*>(out);
    for (int i = blockIdx.x * blockDim.x + t; i < n4;
         i += gridDim.x * blockDim.x) {
        int c4 = (i & 15) * 4;
        float4 v = y4[i];
        v.x = fmaxf(fmaf(v.x, sc[c4 + 0], sh[c4 + 0]), 0.f);
        v.y = fmaxf(fmaf(v.y, sc[c4 + 1], sh[c4 + 1]), 0.f);
        v.z = fmaxf(fmaf(v.z, sc[c4 + 2], sh[c4 + 2]), 0.f);
        v.w = fmaxf(fmaf(v.w, sc[c4 + 3], sh[c4 + 3]), 0.f);
        o4[i] = v;
    }
}

// ---------------------------------------------------------------------------
// inputs (metadata order): x, adj_val, W, b, gamma, beta, adj_row, adj_col
extern "C" void kernel_launch(void* const* d_in, const int* in_sizes, int n_in,
                              void* d_out, int out_size) {
    const float* x       = (const float*)d_in[0];
    const float* adj_val = (const float*)d_in[1];
    const float* W       = (const float*)d_in[2];
    const float* b       = (const float*)d_in[3];
    const float* gamma   = (const float*)d_in[4];
    const float* beta    = (const float*)d_in[5];
    const int*   adj_row = (const int*)d_in[6];
    const int*   adj_col = (const int*)d_in[7];
    float* out = (float*)d_out;
    int E = in_sizes[1];

    int n4 = NN * DD / 4;

    k_hist<<<1184, 256>>>(adj_row, E);
    k_scan<<<NSCAN, 256>>>(E);
    k_scatter<<<1184, 256>>>(adj_row, adj_col, adj_val, E);
    k_spmm_csr<<<(NN + 15) / 16, 256>>>(x);
    k_gemm_stats<<<(NN + 63) / 64, 256>>>(x, W, b);
    k_norm<<<1184, 256>>>(out, gamma, beta, n4);
}